// round 2
// baseline (speedup 1.0000x reference)
#include <cuda_runtime.h>
#include <math.h>

// Problem constants (B,T,I,H,O fixed by the dataset)
#define BDIM 128
#define TDIM 512
#define IDIM 4
#define HDIM 512
#define ODIM 3
#define NREGC 256          // round(H * 0.5)

// Decomposition: 16 clusters x 8 CTAs. Cluster = one M-tile of 8 batch rows.
// Each CTA owns a 64-column slice of W_rec (persistent in smem).
#define GM 16              // M-tiles (clusters)
#define GN 8               // CTAs per cluster (column slices)
#define GRID (GM * GN)     // 128 CTAs
#define NTHREADS 512
#define MT (BDIM / GM)     // 8 rows per cluster
#define NT (HDIM / GN)     // 64 cols per CTA
#define WPAD 516           // padded k-stride for W slice (conflict-free float4)

#define SMEM_FLOATS (NT * WPAD + MT * HDIM)
#define SMEM_BYTES (SMEM_FLOATS * 4)   // 148480 B

// Device-global scratch (no allocations allowed)
__device__ float g_th[2][BDIM * HDIM];   // tanh(h) double buffer (L2-resident, 512KB)
__device__ float g_regpart[GRID];        // per-CTA regularizer partials

#define CLUSTER_SYNC() do { \
    asm volatile("barrier.cluster.arrive.aligned;" ::: "memory"); \
    asm volatile("barrier.cluster.wait.aligned;"   ::: "memory"); \
} while (0)

// Fast tanh: 1 - 2/(e^{2|x|}+1), sign restored. ~1e-7 abs error (MUFU.EX2 path).
__device__ __forceinline__ float tanh_fast(float x)
{
    float ax = fabsf(x);
    float e  = __expf(2.0f * ax);            // inf for large ax -> r = 1 (correct)
    float r  = 1.0f - __fdividef(2.0f, e + 1.0f);
    return copysignf(r, x);
}

__global__ __launch_bounds__(NTHREADS, 1) __cluster_dims__(GN, 1, 1)
void rnn_cluster_kernel(const float* __restrict__ x,      // (B,T,I)
                        const float* __restrict__ h0,     // (B,H)
                        const float* __restrict__ Wrec,   // (H,H) row k, col n
                        const float* __restrict__ Win,    // (I,H)
                        const float* __restrict__ Wout,   // (H,O)
                        const float* __restrict__ brec,   // (H)
                        const float* __restrict__ bin,    // (H)
                        float* __restrict__ out)
{
    extern __shared__ float smem[];
    float* Wsm = smem;                 // [NT][WPAD]  persistent W_rec slice (col-major over n)
    float* Asm = smem + NT * WPAD;     // [MT][HDIM]  per-step tanh(h) stage

    const int tid    = threadIdx.x;
    const int w      = tid >> 5;
    const int lane   = tid & 31;
    const int bx     = blockIdx.x;
    const int gm     = bx / GN;        // cluster id (M-tile)
    const int gn     = bx % GN;        // rank in cluster (N-slice)

    const int rloc = tid >> 6;         // 0..7  local row
    const int cloc = tid & 63;         // 0..63 local col
    const int row  = gm * MT + rloc;   // owned batch row
    const int n    = gn * NT + cloc;   // owned hidden column

    float* out_y   = out;                                   // (B,T,O)
    float* out_hs  = out + (size_t)BDIM * TDIM * ODIM;      // (T+1,B,H)

    // ---- stage W_rec slice into smem, transposed to [c][k] ----
    for (int idx = tid; idx < HDIM * NT; idx += NTHREADS) {
        int c = idx & (NT - 1);
        int k = idx >> 6;
        Wsm[c * WPAD + k] = Wrec[(size_t)k * HDIM + gn * NT + c];
    }

    // ---- persistent per-thread state ----
    const float win0 = Win[0 * HDIM + n];
    const float win1 = Win[1 * HDIM + n];
    const float win2 = Win[2 * HDIM + n];
    const float win3 = Win[3 * HDIM + n];
    const float bsum = brec[n] + bin[n];
    const bool  doreg = (n < NREGC);

    float h  = h0[(size_t)row * HDIM + n];
    float zp = 0.0f;
    float racc = 0.0f;

    // hidden_states[0] = h0 ; th[0] = tanh(h0)
    __stcg(&out_hs[(size_t)row * HDIM + n], h);
    __stcg(&g_th[0][row * HDIM + n], tanh_fast(h));

    CLUSTER_SYNC();   // also orders Wsm stores (acts as CTA barrier)

    // =========================== main recurrence ===========================
    for (int t = 0; t < TDIM; ++t) {
        // stage tanh(h_prev) rows for this cluster's M-tile (16KB from L2)
        {
            const float4* src = (const float4*)(g_th[t & 1] + (size_t)gm * MT * HDIM);
            float4* dst = (float4*)Asm;
            #pragma unroll
            for (int i = 0; i < (MT * HDIM / 4) / NTHREADS; ++i)
                dst[tid + i * NTHREADS] = __ldcg(&src[tid + i * NTHREADS]);
        }
        // prefetch input drive (broadcast within row's threads)
        float4 xv = *(const float4*)(x + ((size_t)row * TDIM + t) * IDIM);
        __syncthreads();

        // z[row][n] = tanh(h_prev[row]) . W_rec[:, n]   (K = 512)
        const float* A  = Asm + rloc * HDIM;
        const float* Wr = Wsm + cloc * WPAD;
        float za = 0.f, zb = 0.f;
        #pragma unroll 8
        for (int k = 0; k < HDIM; k += 4) {
            float4 a  = *(const float4*)(A + k);
            float4 wv = *(const float4*)(Wr + k);
            za = fmaf(a.x, wv.x, za);
            zb = fmaf(a.y, wv.y, zb);
            za = fmaf(a.z, wv.z, za);
            zb = fmaf(a.w, wv.w, zb);
        }
        float z = (za + zb) + bsum;
        z = fmaf(xv.x, win0, z); z = fmaf(xv.y, win1, z);
        z = fmaf(xv.z, win2, z); z = fmaf(xv.w, win3, z);

        // leaky update (alpha = 0.5)
        float hn = 0.5f * (h + z);

        // regularizer partials
        if (doreg) {
            float d = hn - h;
            racc = fmaf(d, d, racc);
            if (t > 0) { float e = z - zp; racc = fmaf(e, e, racc); }
        }

        // outputs of this step
        __stcg(&out_hs[(size_t)(t + 1) * BDIM * HDIM + (size_t)row * HDIM + n], hn);
        __stcg(&g_th[(t + 1) & 1][row * HDIM + n], tanh_fast(hn));

        h = hn; zp = z;

        CLUSTER_SYNC();   // release g_th stores to cluster peers
    }

    // =========================== regularizer partial per CTA ===========================
    {
        __shared__ float s_red[NTHREADS / 32];
        float r = racc;
        #pragma unroll
        for (int off = 16; off; off >>= 1) r += __shfl_xor_sync(0xffffffffu, r, off);
        if (lane == 0) s_red[w] = r;
        __syncthreads();
        if (tid == 0) {
            float s = 0.f;
            #pragma unroll
            for (int i = 0; i < NTHREADS / 32; ++i) s += s_red[i];
            g_regpart[bx] = s;
        }
    }

    // =========================== outputs epilogue ===========================
    // out[b,t] = h[t+1,b] @ W_out for this cluster's 8 rows; hs visible after last sync.
    float* WoutS = Asm;   // reuse stage buffer: [512][4] padded
    for (int kk = tid; kk < HDIM; kk += NTHREADS) {
        WoutS[kk * 4 + 0] = Wout[kk * 3 + 0];
        WoutS[kk * 4 + 1] = Wout[kk * 3 + 1];
        WoutS[kk * 4 + 2] = Wout[kk * 3 + 2];
        WoutS[kk * 4 + 3] = 0.f;
    }
    __syncthreads();

    // 8 rows x 512 t = 4096 items per cluster; 128 warps per cluster -> 32 each
    const int warp_in_cluster = gn * (NTHREADS / 32) + w;   // 0..127
    for (int i = 0; i < 32; ++i) {
        int p  = warp_in_cluster * 32 + i;
        int tt = p >> 3;               // 0..511
        int bb = gm * MT + (p & 7);    // global batch row
        const float* hrow = out_hs + (size_t)(tt + 1) * BDIM * HDIM + (size_t)bb * HDIM;
        float o0 = 0.f, o1 = 0.f, o2 = 0.f;
        #pragma unroll 4
        for (int k = lane; k < HDIM; k += 32) {
            float  hv = __ldcg(&hrow[k]);
            float4 wv = ((const float4*)WoutS)[k];
            o0 = fmaf(hv, wv.x, o0);
            o1 = fmaf(hv, wv.y, o1);
            o2 = fmaf(hv, wv.z, o2);
        }
        #pragma unroll
        for (int off = 16; off; off >>= 1) {
            o0 += __shfl_xor_sync(0xffffffffu, o0, off);
            o1 += __shfl_xor_sync(0xffffffffu, o1, off);
            o2 += __shfl_xor_sync(0xffffffffu, o2, off);
        }
        if (lane == 0) {
            float* dst = out_y + ((size_t)bb * TDIM + tt) * ODIM;
            dst[0] = o0; dst[1] = o1; dst[2] = o2;
        }
    }
}

// Tiny deterministic reduction of the 128 per-CTA regularizer partials.
__global__ void reg_reduce_kernel(float* __restrict__ out_reg)
{
    __shared__ float s_red[4];
    int tid  = threadIdx.x;          // 128 threads
    int lane = tid & 31;
    int w    = tid >> 5;
    float v = g_regpart[tid];
    #pragma unroll
    for (int off = 16; off; off >>= 1) v += __shfl_xor_sync(0xffffffffu, v, off);
    if (lane == 0) s_red[w] = v;
    __syncthreads();
    if (tid == 0) {
        float s = s_red[0] + s_red[1] + s_red[2] + s_red[3];
        *out_reg = s / ((float)TDIM * (float)BDIM * (float)NREGC);
    }
}

extern "C" void kernel_launch(void* const* d_in, const int* in_sizes, int n_in,
                              void* d_out, int out_size)
{
    (void)in_sizes; (void)n_in; (void)out_size;
    const float* x    = (const float*)d_in[0];
    const float* h0   = (const float*)d_in[1];
    const float* Wrec = (const float*)d_in[2];
    const float* Win  = (const float*)d_in[3];
    const float* Wout = (const float*)d_in[4];
    const float* brec = (const float*)d_in[5];
    const float* bin  = (const float*)d_in[6];
    float* out = (float*)d_out;

    float* out_reg = out + (size_t)BDIM * TDIM * ODIM
                         + (size_t)(TDIM + 1) * BDIM * HDIM;

    cudaFuncSetAttribute(rnn_cluster_kernel,
                         cudaFuncAttributeMaxDynamicSharedMemorySize, SMEM_BYTES);

    rnn_cluster_kernel<<<GRID, NTHREADS, SMEM_BYTES>>>(
        x, h0, Wrec, Win, Wout, brec, bin, out);
    reg_reduce_kernel<<<1, 128>>>(out_reg);
}

// round 3
// speedup vs baseline: 1.4115x; 1.4115x over previous
#include <cuda_runtime.h>
#include <math.h>

// Problem constants (fixed by dataset)
#define BDIM 128
#define TDIM 512
#define IDIM 4
#define HDIM 512
#define ODIM 3
#define NREGC 256          // round(H * 0.5)

// Decomposition: 16 M-groups x 8 CTAs. Group = 8 batch rows; CTA = 64 W columns.
#define GM 16
#define GN 8
#define GRID (GM * GN)     // 128 CTAs, 1 per SM
#define NTHREADS 512
#define MT (BDIM / GM)     // 8 rows per group
#define NT (HDIM / GN)     // 64 cols per CTA
#define KC (HDIM / 8)      // 64 k-elements per thread ( = 16 float4 in registers )

// Device-global scratch (no allocations allowed)
__device__ float g_th[2][BDIM * HDIM];   // tanh(h) double buffer (512KB, L2-resident)
__device__ unsigned g_flags[GRID];       // per-CTA epoch flags (monotonic)
__device__ float g_regpart[GRID];        // per-CTA regularizer partials

// Fast tanh: 1 - 2/(e^{2|x|}+1), sign restored (~1e-7 abs err, MUFU path)
__device__ __forceinline__ float tanh_fast(float x)
{
    float ax = fabsf(x);
    float e  = __expf(2.0f * ax);
    float r  = 1.0f - __fdividef(2.0f, e + 1.0f);
    return copysignf(r, x);
}

__global__ __launch_bounds__(NTHREADS, 1)
void rnn_persistent_kernel(const float* __restrict__ x,      // (B,T,I)
                           const float* __restrict__ h0,     // (B,H)
                           const float* __restrict__ Wrec,   // (H,H) k-major rows
                           const float* __restrict__ Win,    // (I,H)
                           const float* __restrict__ Wout,   // (H,O)
                           const float* __restrict__ brec,   // (H)
                           const float* __restrict__ bin,    // (H)
                           float* __restrict__ out)
{
    __shared__ float Asm[MT * HDIM];            // 16KB tanh(h_prev) stage
    __shared__ float s_red[NTHREADS / 32];

    const int tid  = threadIdx.x;
    const int w    = tid >> 5;
    const int lane = tid & 31;
    const int bx   = blockIdx.x;
    const int gm   = bx / GN;           // M-group id
    const int gn   = bx % GN;           // N-slice rank within group

    const int kc = lane & 7;            // k-chunk 0..7  (64 k's each)
    const int cl = lane >> 3;           // 0..3
    const int c  = w * 4 + cl;          // local column 0..63
    const int n  = gn * NT + c;         // owned hidden column
    const int row = gm * MT + kc;       // owned batch row (after reduction)

    float* out_y  = out;                                   // (B,T,O)
    float* out_hs = out + (size_t)BDIM * TDIM * ODIM;      // (T+1,B,H)
    float* out_reg = out_hs + (size_t)(TDIM + 1) * BDIM * HDIM;

    // ---- epoch base (all flags equal at entry; monotonic across graph replays) ----
    __shared__ unsigned s_base;
    if (tid == 0) s_base = *((volatile unsigned*)&g_flags[bx]);
    __syncthreads();
    const unsigned base = s_base;

    // ---- load this thread's persistent W_rec registers (rotated by kc to
    //      make the A shared-memory reads bank-conflict-free) ----
    float4 w4[16];
    #pragma unroll
    for (int i = 0; i < 16; ++i) {
        int rot = (i + kc) & 15;                  // k4 index within chunk
        int k   = kc * KC + rot * 4;              // global k of first elem
        w4[i].x = Wrec[(size_t)(k + 0) * HDIM + n];
        w4[i].y = Wrec[(size_t)(k + 1) * HDIM + n];
        w4[i].z = Wrec[(size_t)(k + 2) * HDIM + n];
        w4[i].w = Wrec[(size_t)(k + 3) * HDIM + n];
    }

    const float win0 = Win[0 * HDIM + n];
    const float win1 = Win[1 * HDIM + n];
    const float win2 = Win[2 * HDIM + n];
    const float win3 = Win[3 * HDIM + n];
    const float bsum = brec[n] + bin[n];
    const bool  doreg = (n < NREGC);

    float h  = h0[(size_t)row * HDIM + n];
    float zp = 0.0f;
    float racc = 0.0f;

    // hidden_states[0] = h0 ; th[0] = tanh(h0)
    __stcg(&out_hs[(size_t)row * HDIM + n], h);
    __stcg(&g_th[0][row * HDIM + n], tanh_fast(h));

    unsigned barcnt = 0;

    // ---- group barrier: sync only the 8 CTAs sharing this M-group ----
    auto group_barrier = [&](unsigned target) {
        __syncthreads();
        if (tid == 0) {
            __threadfence();
            *((volatile unsigned*)&g_flags[bx]) = target;
        }
        if (tid < GN) {
            while ((int)(*((volatile unsigned*)&g_flags[gm * GN + tid]) - target) < 0) { }
        }
        __threadfence();
        __syncthreads();
    };

    group_barrier(base + (++barcnt));

    // =========================== main recurrence ===========================
    for (int t = 0; t < TDIM; ++t) {
        // prefetch input drive for owned row (L2-resident x)
        float4 xv = __ldcg((const float4*)(x + ((size_t)row * TDIM + t) * IDIM));

        // stage tanh(h_prev) for this group's 8 rows (16KB from L2)
        {
            const float4* src = (const float4*)(g_th[t & 1] + (size_t)gm * MT * HDIM);
            float4* dst = (float4*)Asm;
            dst[tid]            = __ldcg(&src[tid]);
            dst[tid + NTHREADS] = __ldcg(&src[tid + NTHREADS]);
        }
        __syncthreads();

        // partial GEMM: acc[r] = sum over this thread's k-chunk of A[r][k]*W[k][n]
        float acc[MT];
        #pragma unroll
        for (int r = 0; r < MT; ++r) acc[r] = 0.0f;

        const float* Ab = Asm + kc * KC;
        #pragma unroll
        for (int i = 0; i < 16; ++i) {
            const float4 wv = w4[i];
            const int rot = (i + kc) & 15;
            const float* Ap = Ab + rot * 4;
            #pragma unroll
            for (int r = 0; r < MT; ++r) {
                float4 a = *(const float4*)(Ap + r * HDIM);
                acc[r] = fmaf(a.x, wv.x, acc[r]);
                acc[r] = fmaf(a.y, wv.y, acc[r]);
                acc[r] = fmaf(a.z, wv.z, acc[r]);
                acc[r] = fmaf(a.w, wv.w, acc[r]);
            }
        }

        // reduce k-chunks across lanes 0..7 of each lane-group (butterfly)
        #pragma unroll
        for (int r = 0; r < MT; ++r) {
            float v = acc[r];
            v += __shfl_xor_sync(0xffffffffu, v, 1);
            v += __shfl_xor_sync(0xffffffffu, v, 2);
            v += __shfl_xor_sync(0xffffffffu, v, 4);
            acc[r] = v;     // every lane now has full sum for (row r, col c)
        }

        // this thread keeps row = kc
        float z = acc[kc] + bsum;
        z = fmaf(xv.x, win0, z); z = fmaf(xv.y, win1, z);
        z = fmaf(xv.z, win2, z); z = fmaf(xv.w, win3, z);

        float hn = 0.5f * (h + z);          // alpha = 0.5

        if (doreg) {
            float d = hn - h;
            racc = fmaf(d, d, racc);
            if (t > 0) { float e = z - zp; racc = fmaf(e, e, racc); }
        }

        // publish tanh for next step first (it's on the critical path)
        __stcg(&g_th[(t + 1) & 1][row * HDIM + n], tanh_fast(hn));
        __stcg(&out_hs[(size_t)(t + 1) * BDIM * HDIM + (size_t)row * HDIM + n], hn);

        h = hn; zp = z;

        group_barrier(base + (++barcnt));
    }

    // =========================== regularizer partial per CTA ===========================
    {
        float r = racc;
        #pragma unroll
        for (int off = 16; off; off >>= 1) r += __shfl_xor_sync(0xffffffffu, r, off);
        if (lane == 0) s_red[w] = r;
        __syncthreads();
        if (tid == 0) {
            float s = 0.f;
            #pragma unroll
            for (int i = 0; i < NTHREADS / 32; ++i) s += s_red[i];
            *((volatile float*)&g_regpart[bx]) = s;
            __threadfence();
            *((volatile unsigned*)&g_flags[bx]) = base + barcnt + 1;  // final flag
        }
    }

    // Only CTA 0 waits for everyone and produces the scalar (one-sided).
    if (bx == 0) {
        const unsigned target = base + barcnt + 1;
        if (tid < GRID) {
            while ((int)(*((volatile unsigned*)&g_flags[tid]) - target) < 0) { }
        }
        __threadfence();
        __syncthreads();
        if (tid == 0) {
            float s = 0.f;
            for (int i = 0; i < GRID; ++i) s += g_regpart[i];
            *out_reg = s / ((float)TDIM * (float)BDIM * (float)NREGC);
        }
    }

    // =========================== outputs epilogue ===========================
    // out[b,t] = hs[t+1,b] @ W_out, restricted to this group's 8 rows
    // (their stores are ordered by the final group barrier of the loop).
    __syncthreads();
    float* WoutS = Asm;   // reuse stage buffer: [512][4]
    for (int kk = tid; kk < HDIM; kk += NTHREADS) {
        WoutS[kk * 4 + 0] = Wout[kk * 3 + 0];
        WoutS[kk * 4 + 1] = Wout[kk * 3 + 1];
        WoutS[kk * 4 + 2] = Wout[kk * 3 + 2];
        WoutS[kk * 4 + 3] = 0.f;
    }
    __syncthreads();

    // group work: 8 rows x 512 t = 4096 items over 8 CTAs -> 512 per CTA -> 32 per warp
    for (int i = 0; i < 32; ++i) {
        int p  = (gn * (NTHREADS / 32) + w) * 32 + i;     // 0..4095 within group
        int tt = p >> 3;
        int bb = gm * MT + (p & 7);
        const float* hrow = out_hs + (size_t)(tt + 1) * BDIM * HDIM + (size_t)bb * HDIM;
        float o0 = 0.f, o1 = 0.f, o2 = 0.f;
        #pragma unroll 4
        for (int k = lane; k < HDIM; k += 32) {
            float  hv = __ldcg(&hrow[k]);
            float4 wv = ((const float4*)WoutS)[k];
            o0 = fmaf(hv, wv.x, o0);
            o1 = fmaf(hv, wv.y, o1);
            o2 = fmaf(hv, wv.z, o2);
        }
        #pragma unroll
        for (int off = 16; off; off >>= 1) {
            o0 += __shfl_xor_sync(0xffffffffu, o0, off);
            o1 += __shfl_xor_sync(0xffffffffu, o1, off);
            o2 += __shfl_xor_sync(0xffffffffu, o2, off);
        }
        if (lane == 0) {
            float* dst = out_y + ((size_t)bb * TDIM + tt) * ODIM;
            dst[0] = o0; dst[1] = o1; dst[2] = o2;
        }
    }
}

extern "C" void kernel_launch(void* const* d_in, const int* in_sizes, int n_in,
                              void* d_out, int out_size)
{
    (void)in_sizes; (void)n_in; (void)out_size;
    const float* x    = (const float*)d_in[0];
    const float* h0   = (const float*)d_in[1];
    const float* Wrec = (const float*)d_in[2];
    const float* Win  = (const float*)d_in[3];
    const float* Wout = (const float*)d_in[4];
    const float* brec = (const float*)d_in[5];
    const float* bin  = (const float*)d_in[6];
    float* out = (float*)d_out;

    rnn_persistent_kernel<<<GRID, NTHREADS>>>(
        x, h0, Wrec, Win, Wout, brec, bin, out);
}

// round 8
// speedup vs baseline: 2.0137x; 1.4266x over previous
#include <cuda_runtime.h>
#include <math.h>

// Problem constants (fixed by dataset)
#define BDIM 128
#define TDIM 512
#define IDIM 4
#define HDIM 512
#define ODIM 3
#define NREGC 256          // round(H * 0.5)

// Decomposition: 16 M-groups x 8 CTAs; CTA = 64 cols, group = 8 batch rows.
#define GM 16
#define GN 8
#define GRID (GM * GN)     // 128 CTAs, 1/SM
#define NTHREADS 256       // 8 warps
#define MT (BDIM / GM)     // 8 rows per group

// Per-thread tile: 4 cols x 32 k (W = 128 floats in regs), 8 rows
// 16-lane k-reduction groups; each thread ends owning 2 outputs (same row).

__device__ float g_th[2][BDIM * HDIM];   // tanh(h) double buffer (L2-resident)
__device__ unsigned g_flags[GRID];       // per-CTA epoch flags (monotonic)
__device__ float g_regpart[GRID];        // per-CTA regularizer partials

__device__ __forceinline__ float tanh_fast(float x)
{
    float ax = fabsf(x);
    float e  = __expf(2.0f * ax);
    float r  = 1.0f - __fdividef(2.0f, e + 1.0f);
    return copysignf(r, x);
}

__device__ __forceinline__ unsigned long long pack2(float lo, float hi)
{
    return (unsigned long long)__float_as_uint(lo)
         | ((unsigned long long)__float_as_uint(hi) << 32);
}
__device__ __forceinline__ float lo2(unsigned long long u) { return __uint_as_float((unsigned)u); }
__device__ __forceinline__ float hi2(unsigned long long u) { return __uint_as_float((unsigned)(u >> 32)); }

// Packed dual-FMA (sm_100+): acc.{lo,hi} += a.{lo,hi} * w.{lo,hi}
__device__ __forceinline__ void ffma2(unsigned long long& acc,
                                      unsigned long long a,
                                      unsigned long long w)
{
    asm("fma.rn.f32x2 %0, %1, %2, %0;" : "+l"(acc) : "l"(a), "l"(w));
}

__global__ __launch_bounds__(NTHREADS, 1)
void rnn_persistent_kernel(const float* __restrict__ x,      // (B,T,I)
                           const float* __restrict__ h0,     // (B,H)
                           const float* __restrict__ Wrec,   // (H,H)
                           const float* __restrict__ Win,    // (I,H)
                           const float* __restrict__ Wout,   // (H,O)
                           const float* __restrict__ brec,   // (H)
                           const float* __restrict__ bin,    // (H)
                           float* __restrict__ out)
{
    __shared__ __align__(16) float Asm[MT * HDIM];   // 16KB tanh(h_prev) stage
    __shared__ float s_red[NTHREADS / 32];
    __shared__ unsigned s_base;

    const int tid  = threadIdx.x;
    const int w    = tid >> 5;          // warp 0..7
    const int lane = tid & 31;
    const int bx   = blockIdx.x;
    const int gm   = bx / GN;           // M-group
    const int gn   = bx % GN;           // N-slice rank

    const int g      = lane & 15;       // reduction-group lane (== k-chunk)
    const int grp    = lane >> 4;       // 0/1
    const int kc     = g;               // k in [kc*32, kc*32+32)
    const int colgrp = w * 2 + grp;     // 0..15 -> 4 cols each
    const int nbase  = gn * 64 + colgrp * 4;

    // Outputs owned after reduction (both same row):
    const int row = gm * MT + (g & 7);
    const int n0  = nbase + (g >> 3);
    const int n1  = n0 + 2;

    float* out_y   = out;                                   // (B,T,O)
    float* out_hs  = out + (size_t)BDIM * TDIM * ODIM;      // (T+1,B,H)
    float* out_reg = out_hs + (size_t)(TDIM + 1) * BDIM * HDIM;

    if (tid == 0) s_base = *((volatile unsigned*)&g_flags[bx]);
    __syncthreads();
    const unsigned base = s_base;

    // ---- persistent W registers: wreg[cl][j] packs (k=kc*32+2j, k+1) for col nbase+cl
    unsigned long long wreg[4][16];
    #pragma unroll
    for (int j = 0; j < 16; ++j) {
        int k = kc * 32 + j * 2;
        float4 wa = *(const float4*)&Wrec[(size_t)k * HDIM + nbase];
        float4 wb = *(const float4*)&Wrec[(size_t)(k + 1) * HDIM + nbase];
        wreg[0][j] = pack2(wa.x, wb.x);
        wreg[1][j] = pack2(wa.y, wb.y);
        wreg[2][j] = pack2(wa.z, wb.z);
        wreg[3][j] = pack2(wa.w, wb.w);
    }

    const float4 winA = { Win[0*HDIM + n0], Win[1*HDIM + n0], Win[2*HDIM + n0], Win[3*HDIM + n0] };
    const float4 winB = { Win[0*HDIM + n1], Win[1*HDIM + n1], Win[2*HDIM + n1], Win[3*HDIM + n1] };
    const float bsum0 = brec[n0] + bin[n0];
    const float bsum1 = brec[n1] + bin[n1];
    const bool  dor0 = (n0 < NREGC);
    const bool  dor1 = (n1 < NREGC);

    float hA = h0[(size_t)row * HDIM + n0];
    float hB = h0[(size_t)row * HDIM + n1];
    float zpA = 0.f, zpB = 0.f, racc = 0.f;

    __stcg(&out_hs[(size_t)row * HDIM + n0], hA);
    __stcg(&out_hs[(size_t)row * HDIM + n1], hB);
    __stcg(&g_th[0][row * HDIM + n0], tanh_fast(hA));
    __stcg(&g_th[0][row * HDIM + n1], tanh_fast(hB));

    unsigned barcnt = 0;
    auto group_barrier = [&](unsigned target) {
        __syncthreads();
        if (tid == 0) {
            __threadfence();                               // order data -> flag
            *((volatile unsigned*)&g_flags[bx]) = target;
        }
        if (tid < GN) {
            while ((int)(*((volatile unsigned*)&g_flags[gm * GN + tid]) - target) < 0) { }
        }
        __syncthreads();   // data read via ldcg from L2; no reader fence needed
    };

    group_barrier(base + (++barcnt));

    // =========================== main recurrence ===========================
    for (int t = 0; t < TDIM; ++t) {
        float4 xv = __ldcg((const float4*)(x + ((size_t)row * TDIM + t) * IDIM));

        // stage tanh(h_prev): 16KB, 4 float4 per thread
        {
            const float4* src = (const float4*)(g_th[t & 1] + (size_t)gm * MT * HDIM);
            float4* dst = (float4*)Asm;
            #pragma unroll
            for (int i = 0; i < 4; ++i)
                dst[tid + i * NTHREADS] = __ldcg(&src[tid + i * NTHREADS]);
        }
        __syncthreads();

        // GEMM partials, row-at-a-time: only 4 packed accs live at once
        // (spill-proof vs. the 32-acc variant; identical FMA order per output).
        float v[32];                        // v[c*8 + r]
        #pragma unroll
        for (int r = 0; r < MT; ++r) {
            unsigned long long a0 = 0ull, a1 = 0ull, a2 = 0ull, a3 = 0ull;
            const ulonglong2* Ar = (const ulonglong2*)(Asm + r * HDIM + kc * 32);
            #pragma unroll
            for (int i = 0; i < 8; ++i) {
                const int ie = (i + kc) & 7;               // bank-conflict-free rotation
                ulonglong2 a = Ar[ie];
                ffma2(a0, a.x, wreg[0][2*ie]);
                ffma2(a0, a.y, wreg[0][2*ie+1]);
                ffma2(a1, a.x, wreg[1][2*ie]);
                ffma2(a1, a.y, wreg[1][2*ie+1]);
                ffma2(a2, a.x, wreg[2][2*ie]);
                ffma2(a2, a.y, wreg[2][2*ie+1]);
                ffma2(a3, a.x, wreg[3][2*ie]);
                ffma2(a3, a.y, wreg[3][2*ie+1]);
            }
            v[r]      = lo2(a0) + hi2(a0);
            v[8 + r]  = lo2(a1) + hi2(a1);
            v[16 + r] = lo2(a2) + hi2(a2);
            v[24 + r] = lo2(a3) + hi2(a3);
        }

        // 16-lane value-halving butterfly over the two col-banks of v
        int cnt = 16;
        #pragma unroll
        for (int s = 8; s >= 1; s >>= 1) {
            const int half = cnt >> 1;
            const bool hi = (g & s) != 0;
            #pragma unroll
            for (int b = 0; b < 2; ++b) {
                #pragma unroll
                for (int j = 0; j < 8; ++j) {
                    if (j < half) {
                        float send = hi ? v[b*16 + j] : v[b*16 + j + half];
                        float recv = __shfl_xor_sync(0xffffffffu, send, s);
                        float keep = hi ? v[b*16 + j + half] : v[b*16 + j];
                        v[b*16 + j] = keep + recv;
                    }
                }
            }
            cnt = half;
        }
        // lane g owns: v[0] -> (row, n0), v[16] -> (row, n1)

        float zA = v[0]  + bsum0;
        float zB = v[16] + bsum1;
        zA = fmaf(xv.x, winA.x, zA); zA = fmaf(xv.y, winA.y, zA);
        zA = fmaf(xv.z, winA.z, zA); zA = fmaf(xv.w, winA.w, zA);
        zB = fmaf(xv.x, winB.x, zB); zB = fmaf(xv.y, winB.y, zB);
        zB = fmaf(xv.z, winB.z, zB); zB = fmaf(xv.w, winB.w, zB);

        float hnA = 0.5f * (hA + zA);
        float hnB = 0.5f * (hB + zB);

        if (dor0) {
            float d = hnA - hA; racc = fmaf(d, d, racc);
            if (t > 0) { float e = zA - zpA; racc = fmaf(e, e, racc); }
        }
        if (dor1) {
            float d = hnB - hB; racc = fmaf(d, d, racc);
            if (t > 0) { float e = zB - zpB; racc = fmaf(e, e, racc); }
        }

        // publish tanh first (critical path), then hidden state
        float* thn = g_th[(t + 1) & 1];
        __stcg(&thn[row * HDIM + n0], tanh_fast(hnA));
        __stcg(&thn[row * HDIM + n1], tanh_fast(hnB));
        size_t off = (size_t)(t + 1) * BDIM * HDIM + (size_t)row * HDIM;
        __stcg(&out_hs[off + n0], hnA);
        __stcg(&out_hs[off + n1], hnB);

        hA = hnA; hB = hnB; zpA = zA; zpB = zB;

        group_barrier(base + (++barcnt));
    }

    // ---- regularizer partial per CTA, then one-sided final flag ----
    {
        float r = racc;
        #pragma unroll
        for (int off = 16; off; off >>= 1) r += __shfl_xor_sync(0xffffffffu, r, off);
        if (lane == 0) s_red[w] = r;
        __syncthreads();
        if (tid == 0) {
            float s = 0.f;
            #pragma unroll
            for (int i = 0; i < NTHREADS / 32; ++i) s += s_red[i];
            *((volatile float*)&g_regpart[bx]) = s;
            __threadfence();
            *((volatile unsigned*)&g_flags[bx]) = base + barcnt + 1;
        }
    }

    if (bx == 0) {
        const unsigned target = base + barcnt + 1;
        if (tid < GRID) {
            while ((int)(*((volatile unsigned*)&g_flags[tid]) - target) < 0) { }
        }
        __syncthreads();
        if (tid == 0) {
            float s = 0.f;
            for (int i = 0; i < GRID; ++i)
                s += *((volatile float*)&g_regpart[i]);
            *out_reg = s / ((float)TDIM * (float)BDIM * (float)NREGC);
        }
    }

    // ---- outputs epilogue: out[b,t] = hs[t+1,b] @ W_out (group's 8 rows) ----
    __syncthreads();
    float* WoutS = Asm;   // [512][4]
    for (int kk = tid; kk < HDIM; kk += NTHREADS) {
        WoutS[kk * 4 + 0] = Wout[kk * 3 + 0];
        WoutS[kk * 4 + 1] = Wout[kk * 3 + 1];
        WoutS[kk * 4 + 2] = Wout[kk * 3 + 2];
        WoutS[kk * 4 + 3] = 0.f;
    }
    __syncthreads();

    // 4096 items per group / 8 CTAs / 8 warps = 64 per warp
    for (int i = 0; i < 64; ++i) {
        int p  = (gn * (NTHREADS / 32) + w) * 64 + i;
        int tt = p >> 3;
        int bb = gm * MT + (p & 7);
        const float* hrow = out_hs + (size_t)(tt + 1) * BDIM * HDIM + (size_t)bb * HDIM;
        float o0 = 0.f, o1 = 0.f, o2 = 0.f;
        #pragma unroll 4
        for (int k = lane; k < HDIM; k += 32) {
            float  hv = __ldcg(&hrow[k]);
            float4 wv = ((const float4*)WoutS)[k];
            o0 = fmaf(hv, wv.x, o0);
            o1 = fmaf(hv, wv.y, o1);
            o2 = fmaf(hv, wv.z, o2);
        }
        #pragma unroll
        for (int off = 16; off; off >>= 1) {
            o0 += __shfl_xor_sync(0xffffffffu, o0, off);
            o1 += __shfl_xor_sync(0xffffffffu, o1, off);
            o2 += __shfl_xor_sync(0xffffffffu, o2, off);
        }
        if (lane == 0) {
            float* dst = out_y + ((size_t)bb * TDIM + tt) * ODIM;
            dst[0] = o0; dst[1] = o1; dst[2] = o2;
        }
    }
}

extern "C" void kernel_launch(void* const* d_in, const int* in_sizes, int n_in,
                              void* d_out, int out_size)
{
    (void)in_sizes; (void)n_in; (void)out_size;
    const float* x    = (const float*)d_in[0];
    const float* h0   = (const float*)d_in[1];
    const float* Wrec = (const float*)d_in[2];
    const float* Win  = (const float*)d_in[3];
    const float* Wout = (const float*)d_in[4];
    const float* brec = (const float*)d_in[5];
    const float* bin  = (const float*)d_in[6];
    float* out = (float*)d_out;

    rnn_persistent_kernel<<<GRID, NTHREADS>>>(
        x, h0, Wrec, Win, Wout, brec, bin, out);
}

// round 9
// speedup vs baseline: 2.4256x; 1.2046x over previous
#include <cuda_runtime.h>
#include <math.h>

// Problem constants (fixed by dataset)
#define BDIM 128
#define TDIM 512
#define IDIM 4
#define HDIM 512
#define ODIM 3
#define NREGC 256          // round(H * 0.5)

// Decomposition: 16 M-groups x 8 CTAs; CTA = 64 cols, group = 8 batch rows.
#define GM 16
#define GN 8
#define GRID (GM * GN)     // 128 CTAs, 1/SM
#define NTHREADS 512       // 16 warps -> 4/SMSP
#define MT (BDIM / GM)     // 8 rows per group

// Thread tile: cg = warp (4 cols), ks = lane (16 k), 8 rows.
// A stage: 8 rows x 640 words (each 16-float k-slot padded to 20 words -> conflict-free)
#define AROW_W 640
#define A_WORDS (MT * AROW_W)            // 5120
#define SLICE_ULL 34                     // 272B per-thread W slice (32 ull used + pad)
#define SMEM_BYTES (A_WORDS * 4 + NTHREADS * SLICE_ULL * 8)   // 20480 + 139264 = 159744

__device__ float g_th[2][BDIM * HDIM];   // tanh(h) double buffer (L2-resident)
__device__ unsigned g_flags[GRID];       // per-CTA epoch flags (monotonic)
__device__ float g_regpart[GRID];        // per-CTA regularizer partials

__device__ __forceinline__ float tanh_fast(float x)
{
    float ax = fabsf(x);
    float e  = __expf(2.0f * ax);
    float r  = 1.0f - __fdividef(2.0f, e + 1.0f);
    return copysignf(r, x);
}

__device__ __forceinline__ unsigned long long pack2(float lo, float hi)
{
    return (unsigned long long)__float_as_uint(lo)
         | ((unsigned long long)__float_as_uint(hi) << 32);
}
__device__ __forceinline__ float lo2(unsigned long long u) { return __uint_as_float((unsigned)u); }
__device__ __forceinline__ float hi2(unsigned long long u) { return __uint_as_float((unsigned)(u >> 32)); }

__device__ __forceinline__ void ffma2(unsigned long long& acc,
                                      unsigned long long a,
                                      unsigned long long w)
{
    asm("fma.rn.f32x2 %0, %1, %2, %0;" : "+l"(acc) : "l"(a), "l"(w));
}

__global__ __launch_bounds__(NTHREADS, 1)
void rnn_persistent_kernel(const float* __restrict__ x,      // (B,T,I)
                           const float* __restrict__ h0,     // (B,H)
                           const float* __restrict__ Wrec,   // (H,H)
                           const float* __restrict__ Win,    // (I,H)
                           const float* __restrict__ Wout,   // (H,O)
                           const float* __restrict__ brec,   // (H)
                           const float* __restrict__ bin,    // (H)
                           float* __restrict__ out)
{
    extern __shared__ __align__(16) float smem[];
    float* Asm = smem;                                   // [8][640] words
    unsigned long long* Wbase = (unsigned long long*)(smem + A_WORDS);

    __shared__ float s_red[NTHREADS / 32];
    __shared__ unsigned s_base;

    const int tid  = threadIdx.x;
    const int w    = tid >> 5;          // warp 0..15  == colgroup (4 cols)
    const int lane = tid & 31;          // == k-chunk (16 k each)
    const int bx   = blockIdx.x;
    const int gm   = bx / GN;
    const int gn   = bx % GN;

    const int nbase = gn * 64 + w * 4;
    const int n     = nbase + (lane >> 3);     // owned column after reduction
    const int row   = gm * MT + (lane & 7);    // owned batch row after reduction

    float* out_y   = out;
    float* out_hs  = out + (size_t)BDIM * TDIM * ODIM;
    float* out_reg = out_hs + (size_t)(TDIM + 1) * BDIM * HDIM;

    if (tid == 0) s_base = *((volatile unsigned*)&g_flags[bx]);
    __syncthreads();
    const unsigned base = s_base;

    // ---- stage this thread's private W slice (4 cols x 16 k, packed k-pairs) ----
    // slice layout (ull index u): kb = u>>3, pair = (u&7)>>2, c = u&3
    unsigned long long* Wsl = Wbase + (size_t)tid * SLICE_ULL;
    #pragma unroll
    for (int u = 0; u < 32; ++u) {
        int kb = u >> 3, p = (u >> 2) & 1, c = u & 3;
        int k  = lane * 16 + kb * 4 + p * 2;
        Wsl[u] = pack2(Wrec[(size_t)k * HDIM + nbase + c],
                       Wrec[(size_t)(k + 1) * HDIM + nbase + c]);
    }
    const ulonglong2* Wsl2 = (const ulonglong2*)Wsl;     // 2 ull per 16B

    // ---- persistent per-thread state (one element) ----
    const float4 win = { Win[0*HDIM + n], Win[1*HDIM + n], Win[2*HDIM + n], Win[3*HDIM + n] };
    const float bsum = brec[n] + bin[n];
    const bool  doreg = (n < NREGC);

    float h  = h0[(size_t)row * HDIM + n];
    float zp = 0.f, racc = 0.f;

    __stcg(&out_hs[(size_t)row * HDIM + n], h);
    __stcg(&g_th[0][row * HDIM + n], tanh_fast(h));

    unsigned barcnt = 0;
    auto group_barrier = [&](unsigned target) {
        __syncthreads();
        if (tid == 0) {
            __threadfence();
            *((volatile unsigned*)&g_flags[bx]) = target;
        }
        if (tid < GN) {
            while ((int)(*((volatile unsigned*)&g_flags[gm * GN + tid]) - target) < 0) { }
        }
        __syncthreads();
    };

    group_barrier(base + (++barcnt));

    const ulonglong2* A2 = (const ulonglong2*)Asm;       // u2 index = word/4

    // =========================== main recurrence ===========================
    for (int t = 0; t < TDIM; ++t) {
        float4 xv = __ldcg((const float4*)(x + ((size_t)row * TDIM + t) * IDIM));

        // stage tanh(h_prev) (16KB) into k-slot-padded layout: 2 float4 per thread
        {
            const float4* src = (const float4*)(g_th[t & 1] + (size_t)gm * MT * HDIM);
            #pragma unroll
            for (int e = 0; e < 2; ++e) {
                int q = tid * 2 + e;                      // float4 index 0..1023
                float4 val = __ldcg(&src[q]);
                int r   = q >> 7;                         // 128 float4 per row
                int kw  = (q & 127) * 4;                  // word within row
                *(float4*)&Asm[r * AROW_W + (kw >> 4) * 20 + (kw & 15)] = val;
            }
        }
        __syncthreads();

        // GEMM: acc[c*8+r] packed over k-parity; W from private slice, A broadcast
        unsigned long long acc[32];
        #pragma unroll
        for (int i = 0; i < 32; ++i) acc[i] = 0ull;

        #pragma unroll
        for (int kb = 0; kb < 4; ++kb) {
            ulonglong2 wA = Wsl2[kb * 4 + 0];    // pair0: c0,c1
            ulonglong2 wB = Wsl2[kb * 4 + 1];    // pair0: c2,c3
            ulonglong2 wC = Wsl2[kb * 4 + 2];    // pair1: c0,c1
            ulonglong2 wD = Wsl2[kb * 4 + 3];    // pair1: c2,c3
            #pragma unroll
            for (int r = 0; r < MT; ++r) {
                ulonglong2 a = A2[r * 160 + lane * 5 + kb];   // 4 k values
                ffma2(acc[0*8 + r], a.x, wA.x);
                ffma2(acc[1*8 + r], a.x, wA.y);
                ffma2(acc[2*8 + r], a.x, wB.x);
                ffma2(acc[3*8 + r], a.x, wB.y);
                ffma2(acc[0*8 + r], a.y, wC.x);
                ffma2(acc[1*8 + r], a.y, wC.y);
                ffma2(acc[2*8 + r], a.y, wD.x);
                ffma2(acc[3*8 + r], a.y, wD.y);
            }
        }

        // collapse packed halves
        float v[32];
        #pragma unroll
        for (int i = 0; i < 32; ++i) v[i] = lo2(acc[i]) + hi2(acc[i]);

        // 32-lane value-halving butterfly; lane g ends owning original index g
        int cnt = 32;
        #pragma unroll
        for (int s = 16; s >= 1; s >>= 1) {
            const int half = cnt >> 1;
            const bool hi = (lane & s) != 0;
            #pragma unroll
            for (int j = 0; j < 16; ++j) {
                if (j < half) {
                    float send = hi ? v[j] : v[j + half];
                    float recv = __shfl_xor_sync(0xffffffffu, send, s);
                    float keep = hi ? v[j + half] : v[j];
                    v[j] = keep + recv;
                }
            }
            cnt = half;
        }
        // v[0] = full dot product for (row, n)

        float z = v[0] + bsum;
        z = fmaf(xv.x, win.x, z); z = fmaf(xv.y, win.y, z);
        z = fmaf(xv.z, win.z, z); z = fmaf(xv.w, win.w, z);

        float hn = 0.5f * (h + z);          // alpha = 0.5

        if (doreg) {
            float d = hn - h; racc = fmaf(d, d, racc);
            if (t > 0) { float e = z - zp; racc = fmaf(e, e, racc); }
        }

        __stcg(&g_th[(t + 1) & 1][row * HDIM + n], tanh_fast(hn));
        __stcg(&out_hs[(size_t)(t + 1) * BDIM * HDIM + (size_t)row * HDIM + n], hn);

        h = hn; zp = z;

        group_barrier(base + (++barcnt));
    }

    // ---- regularizer partial per CTA, then one-sided final flag ----
    {
        float r = racc;
        #pragma unroll
        for (int off = 16; off; off >>= 1) r += __shfl_xor_sync(0xffffffffu, r, off);
        if (lane == 0) s_red[w] = r;
        __syncthreads();
        if (tid == 0) {
            float s = 0.f;
            #pragma unroll
            for (int i = 0; i < NTHREADS / 32; ++i) s += s_red[i];
            *((volatile float*)&g_regpart[bx]) = s;
            __threadfence();
            *((volatile unsigned*)&g_flags[bx]) = base + barcnt + 1;
        }
    }

    if (bx == 0) {
        const unsigned target = base + barcnt + 1;
        if (tid < GRID) {
            while ((int)(*((volatile unsigned*)&g_flags[tid]) - target) < 0) { }
        }
        __syncthreads();
        if (tid == 0) {
            float s = 0.f;
            for (int i = 0; i < GRID; ++i)
                s += *((volatile float*)&g_regpart[i]);
            *out_reg = s / ((float)TDIM * (float)BDIM * (float)NREGC);
        }
    }

    // ---- outputs epilogue: out[b,t] = hs[t+1,b] @ W_out (group's 8 rows) ----
    __syncthreads();
    float* WoutS = Asm;   // reuse A stage: [512][4]
    for (int kk = tid; kk < HDIM; kk += NTHREADS) {
        WoutS[kk * 4 + 0] = Wout[kk * 3 + 0];
        WoutS[kk * 4 + 1] = Wout[kk * 3 + 1];
        WoutS[kk * 4 + 2] = Wout[kk * 3 + 2];
        WoutS[kk * 4 + 3] = 0.f;
    }
    __syncthreads();

    // 4096 items per group / 8 CTAs / 16 warps = 32 per warp
    for (int i = 0; i < 32; ++i) {
        int p  = (gn * (NTHREADS / 32) + w) * 32 + i;
        int tt = p >> 3;
        int bb = gm * MT + (p & 7);
        const float* hrow = out_hs + (size_t)(tt + 1) * BDIM * HDIM + (size_t)bb * HDIM;
        float o0 = 0.f, o1 = 0.f, o2 = 0.f;
        #pragma unroll 4
        for (int k = lane; k < HDIM; k += 32) {
            float  hv = __ldcg(&hrow[k]);
            float4 wv = ((const float4*)WoutS)[k];
            o0 = fmaf(hv, wv.x, o0);
            o1 = fmaf(hv, wv.y, o1);
            o2 = fmaf(hv, wv.z, o2);
        }
        #pragma unroll
        for (int off = 16; off; off >>= 1) {
            o0 += __shfl_xor_sync(0xffffffffu, o0, off);
            o1 += __shfl_xor_sync(0xffffffffu, o1, off);
            o2 += __shfl_xor_sync(0xffffffffu, o2, off);
        }
        if (lane == 0) {
            float* dst = out_y + ((size_t)bb * TDIM + tt) * ODIM;
            dst[0] = o0; dst[1] = o1; dst[2] = o2;
        }
    }
}

extern "C" void kernel_launch(void* const* d_in, const int* in_sizes, int n_in,
                              void* d_out, int out_size)
{
    (void)in_sizes; (void)n_in; (void)out_size;
    const float* x    = (const float*)d_in[0];
    const float* h0   = (const float*)d_in[1];
    const float* Wrec = (const float*)d_in[2];
    const float* Win  = (const float*)d_in[3];
    const float* Wout = (const float*)d_in[4];
    const float* brec = (const float*)d_in[5];
    const float* bin  = (const float*)d_in[6];
    float* out = (float*)d_out;

    cudaFuncSetAttribute(rnn_persistent_kernel,
                         cudaFuncAttributeMaxDynamicSharedMemorySize, SMEM_BYTES);

    rnn_persistent_kernel<<<GRID, NTHREADS, SMEM_BYTES>>>(
        x, h0, Wrec, Win, Wout, brec, bin, out);
}